// round 13
// baseline (speedup 1.0000x reference)
#include <cuda_runtime.h>
#include <cuda_bf16.h>
#include <cstdint>

#define DIM   128
#define MAXN  50000
#define NPAD  50176           // MAXN rounded up to multiple of 128 (pad rows)
#define MAXDEG 64
typedef unsigned long long ull;

// ---------------------------------------------------------------------------
// Device globals (no allocation allowed)
// ---------------------------------------------------------------------------
__device__ __align__(16) int   g_deg[MAXN];
__device__ __align__(16) int   g_elist[MAXN * MAXDEG];       // 12.8 MB
__device__ __align__(16) __nv_bfloat16 g_mhi[NPAD * 128];    // mean hi
__device__ __align__(16) __nv_bfloat16 g_mlo[NPAD * 128];    // mean lo
__device__ __align__(16) __nv_bfloat16 g_xhi[NPAD * 128];    // x hi
__device__ __align__(16) __nv_bfloat16 g_xlo[NPAD * 128];    // x lo
__device__ __align__(16) __nv_bfloat16 g_whi[128 * 256];     // W_cat hi, [n][k]
__device__ __align__(16) __nv_bfloat16 g_wlo[128 * 256];     // W_cat lo, [n][k]
__device__ int g_is64;

__device__ __forceinline__ uint32_t smem_u32(const void* p) {
    uint32_t a;
    asm("{ .reg .u64 t; cvta.to.shared.u64 t, %1; cvt.u32.u64 %0, t; }" : "=r"(a) : "l"(p));
    return a;
}
__device__ __forceinline__ void ldm4(uint32_t* r, uint32_t addr) {
    asm volatile("ldmatrix.sync.aligned.m8n8.x4.shared.b16 {%0,%1,%2,%3}, [%4];"
                 : "=r"(r[0]), "=r"(r[1]), "=r"(r[2]), "=r"(r[3]) : "r"(addr));
}
__device__ __forceinline__ void mma16816(float* c, const uint32_t* a, uint32_t b0, uint32_t b1) {
    asm volatile(
        "mma.sync.aligned.m16n8k16.row.col.f32.bf16.bf16.f32 "
        "{%0,%1,%2,%3}, {%4,%5,%6,%7}, {%8,%9}, {%0,%1,%2,%3};"
        : "+f"(c[0]), "+f"(c[1]), "+f"(c[2]), "+f"(c[3])
        : "r"(a[0]), "r"(a[1]), "r"(a[2]), "r"(a[3]), "r"(b0), "r"(b1));
}
__device__ __forceinline__ uint32_t pkbf(__nv_bfloat16 a, __nv_bfloat16 b) {
    __nv_bfloat162 t = __halves2bfloat162(a, b);
    return *reinterpret_cast<uint32_t*>(&t);
}
__device__ __forceinline__ ull split4(float4 v, ull& loOut) {
    __nv_bfloat16 h0 = __float2bfloat16(v.x), h1 = __float2bfloat16(v.y);
    __nv_bfloat16 h2 = __float2bfloat16(v.z), h3 = __float2bfloat16(v.w);
    __nv_bfloat16 e0 = __float2bfloat16(v.x - __bfloat162float(h0));
    __nv_bfloat16 e1 = __float2bfloat16(v.y - __bfloat162float(h1));
    __nv_bfloat16 e2 = __float2bfloat16(v.z - __bfloat162float(h2));
    __nv_bfloat16 e3 = __float2bfloat16(v.w - __bfloat162float(h3));
    loOut = (ull)pkbf(e0, e1) | ((ull)pkbf(e2, e3) << 32);
    return (ull)pkbf(h0, h1) | ((ull)pkbf(h2, h3) << 32);
}
__device__ __forceinline__ void cpa16(uint32_t smem, const void* g) {
    asm volatile("cp.async.ca.shared.global [%0], [%1], 16;" :: "r"(smem), "l"(g));
}
#define CPA_COMMIT() asm volatile("cp.async.commit_group;" ::: "memory")
#define CPA_WAIT(n)  asm volatile("cp.async.wait_group %0;" :: "n"(n) : "memory")

// ---------------------------------------------------------------------------
// Kernel A (merged prep): detect dtype (block 0) + zero g_deg + W split.
// ---------------------------------------------------------------------------
__global__ void prep_kernel(const void* ei_raw, int E, int N,
                            const float* __restrict__ Wl, const float* __restrict__ Wr) {
    int i = blockIdx.x * blockDim.x + threadIdx.x;

    if (blockIdx.x == 0) {
        __shared__ int ok;
        if (threadIdx.x == 0) ok = 1;
        __syncthreads();
        const long long* e64 = (const long long*)ei_raw;
        int probe = (E < 1024) ? E : 1024;
        for (int j = threadIdx.x; j < probe; j += blockDim.x) {
            long long v = e64[j];
            if (v < 0 || v >= (long long)N) atomicExch(&ok, 0);
        }
        __syncthreads();
        if (threadIdx.x == 0) g_is64 = ok;
    }
    if (i < N) g_deg[i] = 0;
    if (i < 128 * 256) {
        int n = i >> 8, k = i & 255;
        float v = (k < 128) ? Wl[n * 128 + k] : Wr[n * 128 + (k - 128)];
        __nv_bfloat16 h  = __float2bfloat16(v);
        __nv_bfloat16 lo = __float2bfloat16(v - __bfloat162float(h));
        g_whi[i] = h;
        g_wlo[i] = lo;
    }
}

// ---------------------------------------------------------------------------
// Kernel B (merged): build edge lists + x hi/lo split (grid-split fusion)
// ---------------------------------------------------------------------------
#define BBLK(E) (((E) + 255) / 256)
#define XBLK    ((NPAD * 32 + 255) / 256)

__global__ void build_xprep_kernel(const void* __restrict__ ei_raw,
                                   const float* __restrict__ x, int E, int N,
                                   int buildBlocks) {
    if ((int)blockIdx.x < buildBlocks) {
        int e = blockIdx.x * blockDim.x + threadIdx.x;
        if (e >= E) return;
        long long s, d;
        if (g_is64) {
            const long long* ei = (const long long*)ei_raw;
            s = __ldg(&ei[e]);  d = __ldg(&ei[E + e]);
        } else {
            const int* ei = (const int*)ei_raw;
            s = __ldg(&ei[e]);  d = __ldg(&ei[E + e]);
        }
        if ((ull)s >= (ull)N || (ull)d >= (ull)N) return;
        int pos = atomicAdd(&g_deg[(int)d], 1);
        if (pos < MAXDEG) g_elist[(int)d * MAXDEG + pos] = (int)s;
    } else {
        int i = (blockIdx.x - buildBlocks) * blockDim.x + threadIdx.x;
        if (i >= NPAD * 32) return;
        int n = i >> 5, q = i & 31;
        float4 v = make_float4(0.f, 0.f, 0.f, 0.f);
        if (n < N) v = __ldg(reinterpret_cast<const float4*>(x) + (size_t)n * 32 + q);
        ull lo, hi = split4(v, lo);
        ((ull*)g_xhi)[(size_t)n * 32 + q] = hi;
        ((ull*)g_xlo)[(size_t)n * 32 + q] = lo;
    }
}

// ---------------------------------------------------------------------------
// Kernel C: pull aggregation — one warp per node (proven; at the LTS floor)
// ---------------------------------------------------------------------------
__global__ void pull_kernel(const float* __restrict__ x, int N) {
    int node = blockIdx.x * (blockDim.x >> 5) + (threadIdx.x >> 5);
    if (node >= NPAD) return;
    int lane = threadIdx.x & 31;

    int deg = (node < N) ? g_deg[node] : 0;
    if (deg > MAXDEG) deg = MAXDEG;
    const int* lst = g_elist + (size_t)node * MAXDEG;
    const float4* x4 = reinterpret_cast<const float4*>(x);

    float4 acc = make_float4(0.f, 0.f, 0.f, 0.f);
    int j = 0;
    for (; j + 4 <= deg; j += 4) {
        int s0 = __ldg(lst + j),     s1 = __ldg(lst + j + 1);
        int s2 = __ldg(lst + j + 2), s3 = __ldg(lst + j + 3);
        float4 v0 = __ldg(&x4[(size_t)s0 * 32 + lane]);
        float4 v1 = __ldg(&x4[(size_t)s1 * 32 + lane]);
        float4 v2 = __ldg(&x4[(size_t)s2 * 32 + lane]);
        float4 v3 = __ldg(&x4[(size_t)s3 * 32 + lane]);
        acc.x += v0.x + v1.x + v2.x + v3.x;
        acc.y += v0.y + v1.y + v2.y + v3.y;
        acc.z += v0.z + v1.z + v2.z + v3.z;
        acc.w += v0.w + v1.w + v2.w + v3.w;
    }
    for (; j < deg; ++j) {
        int s0 = __ldg(lst + j);
        float4 v0 = __ldg(&x4[(size_t)s0 * 32 + lane]);
        acc.x += v0.x; acc.y += v0.y; acc.z += v0.z; acc.w += v0.w;
    }
    float inv = 1.f / fmaxf((float)deg, 1.f);
    acc.x *= inv; acc.y *= inv; acc.z *= inv; acc.w *= inv;
    ull lo, hi = split4(acc, lo);
    ((ull*)g_mhi)[(size_t)node * 32 + lane] = hi;
    ((ull*)g_mlo)[(size_t)node * 32 + lane] = lo;
}

// ---------------------------------------------------------------------------
// Kernel D: mma.sync bf16 GEMM (3-term split) + bias + LayerNorm + ReLU.
// 2-stage cp.async PIPELINE over 8 chunks of K=32: fill(kt+1) overlaps
// compute(kt). Stage = 4 tiles x 128 rows x 80B pitch (5x16B, co-prime with
// 32 banks -> conflict-free ldmatrix). smem 81.5KB -> 2 CTAs/SM.
// ---------------------------------------------------------------------------
#define APITCH 80             // bytes per smem row (40 bf16)
#define TILE_SZ (128 * APITCH)          // 10240
#define T_AHI  0
#define T_ALO  (1 * TILE_SZ)
#define T_BHI  (2 * TILE_SZ)
#define T_BLO  (3 * TILE_SZ)
#define STAGE_SZ (4 * TILE_SZ)          // 40960
#define S_BIAS (2 * STAGE_SZ)           // 81920
#define S_GAM  (S_BIAS + 512)
#define S_BET  (S_GAM + 512)
#define SMEM_TOT (S_BET + 512)          // 83456
#define S_STAGE 0
#define SPITCH 132

extern "C" __global__ void __launch_bounds__(256, 2)
gemm_mma_kernel(const float* __restrict__ bl,
                const float* __restrict__ gamma,
                const float* __restrict__ beta,
                float* __restrict__ out, int N) {
    extern __shared__ char dsm[];
    uint32_t sb = smem_u32(dsm);
    int tid = threadIdx.x;
    int w = tid >> 5, l = tid & 31;
    int wr = w >> 1, wc = w & 1;            // warp tile: rows wr*32, cols wc*64
    int row0 = blockIdx.x * 128;

    if (tid < 128) {
        ((float*)(dsm + S_BIAS))[tid] = bl[tid];
        ((float*)(dsm + S_GAM))[tid]  = gamma[tid];
        ((float*)(dsm + S_BET))[tid]  = beta[tid];
    }

    float acc[2][8][4];
#pragma unroll
    for (int a = 0; a < 2; ++a)
#pragma unroll
        for (int b = 0; b < 8; ++b)
#pragma unroll
            for (int c = 0; c < 4; ++c) acc[a][b][c] = 0.f;

    // ---- pipelined fill helper (K=32 chunk kt into stage st) ----
    auto fill = [&](int st, int kt) {
        const __nv_bfloat16* srcHi = (kt < 4) ? g_mhi : g_xhi;
        const __nv_bfloat16* srcLo = (kt < 4) ? g_mlo : g_xlo;
        int koff = (kt & 3) * 32;           // col offset within 128-wide row
        int kw   = kt * 32;                 // k offset within W (256 wide)
        uint32_t base = sb + st * STAGE_SZ;
        // A: 128 rows x 4 x 16B per tile
        for (int i = tid; i < 512; i += 256) {
            int r = i >> 2, q = i & 3;
            size_t gofs = (size_t)(row0 + r) * 128 + koff + q * 8;
            cpa16(base + T_AHI + r * APITCH + q * 16, srcHi + gofs);
            cpa16(base + T_ALO + r * APITCH + q * 16, srcLo + gofs);
        }
        // B: 128 n-rows x 4 x 16B per tile
        for (int i = tid; i < 512; i += 256) {
            int n = i >> 2, q = i & 3;
            size_t gofs = (size_t)n * 256 + kw + q * 8;
            cpa16(base + T_BHI + n * APITCH + q * 16, g_whi + gofs);
            cpa16(base + T_BLO + n * APITCH + q * 16, g_wlo + gofs);
        }
        CPA_COMMIT();
    };

    fill(0, 0);
    for (int kt = 0; kt < 8; ++kt) {
        int cur = kt & 1;
        if (kt < 7) { fill(cur ^ 1, kt + 1); CPA_WAIT(1); }
        else        { CPA_WAIT(0); }
        __syncthreads();

        uint32_t base = sb + cur * STAGE_SZ;
#pragma unroll
        for (int ks = 0; ks < 2; ++ks) {
            int lrow = (l & 7) + (l & 8);
            int lcol = ks * 16 + ((l & 16) ? 8 : 0);
            uint32_t ah[2][4], al[2][4];
#pragma unroll
            for (int mf = 0; mf < 2; ++mf) {
                int row = wr * 32 + mf * 16 + lrow;
                uint32_t addr = base + T_AHI + row * APITCH + lcol * 2;
                ldm4(ah[mf], addr);
                ldm4(al[mf], addr + (T_ALO - T_AHI));
            }
#pragma unroll
            for (int nb = 0; nb < 4; ++nb) {
                int n = wc * 64 + nb * 16 + lrow;
                uint32_t baddr = base + T_BHI + n * APITCH + lcol * 2;
                uint32_t bh[4], bo[4];
                ldm4(bh, baddr);
                ldm4(bo, baddr + (T_BLO - T_BHI));
#pragma unroll
                for (int mf = 0; mf < 2; ++mf) {
                    float* c0 = acc[mf][2 * nb];
                    float* c1 = acc[mf][2 * nb + 1];
                    mma16816(c0, ah[mf], bh[0], bh[2]);
                    mma16816(c1, ah[mf], bh[1], bh[3]);
                    mma16816(c0, al[mf], bh[0], bh[2]);
                    mma16816(c1, al[mf], bh[1], bh[3]);
                    mma16816(c0, ah[mf], bo[0], bo[2]);
                    mma16816(c1, ah[mf], bo[1], bo[3]);
                }
            }
        }
        __syncthreads();
    }

    // ---- stage accumulators to smem (reuses tile region) ----
    float* stag = (float*)(dsm + S_STAGE);
#pragma unroll
    for (int mf = 0; mf < 2; ++mf) {
#pragma unroll
        for (int nf = 0; nf < 8; ++nf) {
            int r = wr * 32 + mf * 16 + (l >> 2);
            int c = wc * 64 + nf * 8 + (l & 3) * 2;
            const float* cc = acc[mf][nf];
            *(float2*)(stag + r * SPITCH + c)       = make_float2(cc[0], cc[1]);
            *(float2*)(stag + (r + 8) * SPITCH + c) = make_float2(cc[2], cc[3]);
        }
    }
    __syncthreads();

    // ---- LN + ReLU: warp w handles rows w*16 .. w*16+15 ----
    const float4* biasS = (const float4*)(dsm + S_BIAS);
    const float4* gamS  = (const float4*)(dsm + S_GAM);
    const float4* betS  = (const float4*)(dsm + S_BET);
    float4 bb = biasS[l], gg = gamS[l], ee = betS[l];

    for (int r = w * 16; r < w * 16 + 16; ++r) {
        float4 v = *(const float4*)(stag + r * SPITCH + l * 4);
        v.x += bb.x; v.y += bb.y; v.z += bb.z; v.w += bb.w;
        float s = v.x + v.y + v.z + v.w;
#pragma unroll
        for (int m = 1; m < 32; m <<= 1) s += __shfl_xor_sync(0xffffffffu, s, m);
        float mu = s * (1.0f / 128.0f);
        float dx = v.x - mu, dy = v.y - mu, dz = v.z - mu, dw = v.w - mu;
        float q = dx * dx + dy * dy + dz * dz + dw * dw;
#pragma unroll
        for (int m = 1; m < 32; m <<= 1) q += __shfl_xor_sync(0xffffffffu, q, m);
        float rstd = rsqrtf(q * (1.0f / 128.0f) + 1e-5f);

        int g = row0 + r;
        if (g < N) {
            float4 o;
            o.x = fmaxf(fmaf(dx * rstd, gg.x, ee.x), 0.f);
            o.y = fmaxf(fmaf(dy * rstd, gg.y, ee.y), 0.f);
            o.z = fmaxf(fmaf(dz * rstd, gg.z, ee.z), 0.f);
            o.w = fmaxf(fmaf(dw * rstd, gg.w, ee.w), 0.f);
            *(float4*)(out + (size_t)g * 128 + l * 4) = o;
        }
    }
}

// ---------------------------------------------------------------------------
// Launch: prep, build+xprep (fused grid), pull, gemm.
// ---------------------------------------------------------------------------
extern "C" void kernel_launch(void* const* d_in, const int* in_sizes, int n_in,
                              void* d_out, int out_size) {
    const float* x      = (const float*)d_in[0];
    const void*  ei     = d_in[1];
    const float* Wl     = (const float*)d_in[2];
    const float* bl     = (const float*)d_in[3];
    const float* Wr     = (const float*)d_in[4];
    const float* gamma  = (const float*)d_in[5];
    const float* beta   = (const float*)d_in[6];
    float* out          = (float*)d_out;

    int N = in_sizes[0] / DIM;
    int E = in_sizes[1] / 2;

    cudaFuncSetAttribute(gemm_mma_kernel, cudaFuncAttributeMaxDynamicSharedMemorySize, SMEM_TOT);

    {
        int total = (N > 128 * 256) ? N : 128 * 256;
        prep_kernel<<<(total + 255) / 256, 256>>>(ei, E, N, Wl, Wr);
    }
    {
        int bb = BBLK(E);
        build_xprep_kernel<<<bb + XBLK, 256>>>(ei, x, E, N, bb);
    }
    {
        int blocks = (NPAD + 7) / 8;
        pull_kernel<<<blocks, 256>>>(x, N);
    }
    {
        int blocks = (N + 127) / 128;
        gemm_mma_kernel<<<blocks, 256, SMEM_TOT>>>(bl, gamma, beta, out, N);
    }
}

// round 14
// speedup vs baseline: 1.3780x; 1.3780x over previous
#include <cuda_runtime.h>
#include <cuda_fp16.h>
#include <cstdint>

#define DIM   128
#define MAXN  50000
#define NPAD  50176           // MAXN rounded up to multiple of 128 (pad rows)
#define MAXDEG 64
typedef unsigned long long ull;

// ---------------------------------------------------------------------------
// Device globals (no allocation allowed)
// ---------------------------------------------------------------------------
__device__ __align__(16) int    g_deg[MAXN];
__device__ __align__(16) int    g_elist[MAXN * MAXDEG];      // 12.8 MB
__device__ __align__(16) __half g_mh[NPAD * 128];            // mean, fp16
__device__ __align__(16) __half g_xh[NPAD * 128];            // x, fp16
__device__ __align__(16) __half g_wh[128 * 256];             // W_cat, fp16, [n][k]
__device__ int g_is64;

__device__ __forceinline__ uint32_t smem_u32(const void* p) {
    uint32_t a;
    asm("{ .reg .u64 t; cvta.to.shared.u64 t, %1; cvt.u32.u64 %0, t; }" : "=r"(a) : "l"(p));
    return a;
}
__device__ __forceinline__ void ldm4(uint32_t* r, uint32_t addr) {
    asm volatile("ldmatrix.sync.aligned.m8n8.x4.shared.b16 {%0,%1,%2,%3}, [%4];"
                 : "=r"(r[0]), "=r"(r[1]), "=r"(r[2]), "=r"(r[3]) : "r"(addr));
}
__device__ __forceinline__ void mma16816(float* c, const uint32_t* a, uint32_t b0, uint32_t b1) {
    asm volatile(
        "mma.sync.aligned.m16n8k16.row.col.f32.f16.f16.f32 "
        "{%0,%1,%2,%3}, {%4,%5,%6,%7}, {%8,%9}, {%0,%1,%2,%3};"
        : "+f"(c[0]), "+f"(c[1]), "+f"(c[2]), "+f"(c[3])
        : "r"(a[0]), "r"(a[1]), "r"(a[2]), "r"(a[3]), "r"(b0), "r"(b1));
}
__device__ __forceinline__ ull h4(float4 v) {
    __half2 a = __floats2half2_rn(v.x, v.y);
    __half2 b = __floats2half2_rn(v.z, v.w);
    return (ull)(*reinterpret_cast<uint32_t*>(&a)) |
           ((ull)(*reinterpret_cast<uint32_t*>(&b)) << 32);
}
__device__ __forceinline__ void cpa16(uint32_t smem, const void* g) {
    asm volatile("cp.async.ca.shared.global [%0], [%1], 16;" :: "r"(smem), "l"(g));
}
#define CPA_COMMIT() asm volatile("cp.async.commit_group;" ::: "memory")
#define CPA_WAIT0()  asm volatile("cp.async.wait_group 0;" ::: "memory")

// ---------------------------------------------------------------------------
// Kernel A (merged prep): detect dtype (block 0) + zero g_deg + W -> fp16.
// ---------------------------------------------------------------------------
__global__ void prep_kernel(const void* ei_raw, int E, int N,
                            const float* __restrict__ Wl, const float* __restrict__ Wr) {
    int i = blockIdx.x * blockDim.x + threadIdx.x;

    if (blockIdx.x == 0) {
        __shared__ int ok;
        if (threadIdx.x == 0) ok = 1;
        __syncthreads();
        const long long* e64 = (const long long*)ei_raw;
        int probe = (E < 1024) ? E : 1024;
        for (int j = threadIdx.x; j < probe; j += blockDim.x) {
            long long v = e64[j];
            if (v < 0 || v >= (long long)N) atomicExch(&ok, 0);
        }
        __syncthreads();
        if (threadIdx.x == 0) g_is64 = ok;
    }
    if (i < N) g_deg[i] = 0;
    if (i < 128 * 256) {
        int n = i >> 8, k = i & 255;
        float v = (k < 128) ? Wl[n * 128 + k] : Wr[n * 128 + (k - 128)];
        g_wh[i] = __float2half(v);
    }
}

// ---------------------------------------------------------------------------
// Kernel B (merged): build edge lists + x -> fp16 (grid-split fusion)
// ---------------------------------------------------------------------------
#define BBLK(E) (((E) + 255) / 256)
#define XBLK    ((NPAD * 32 + 255) / 256)

__global__ void build_xprep_kernel(const void* __restrict__ ei_raw,
                                   const float* __restrict__ x, int E, int N,
                                   int buildBlocks) {
    if ((int)blockIdx.x < buildBlocks) {
        int e = blockIdx.x * blockDim.x + threadIdx.x;
        if (e >= E) return;
        long long s, d;
        if (g_is64) {
            const long long* ei = (const long long*)ei_raw;
            s = __ldg(&ei[e]);  d = __ldg(&ei[E + e]);
        } else {
            const int* ei = (const int*)ei_raw;
            s = __ldg(&ei[e]);  d = __ldg(&ei[E + e]);
        }
        if ((ull)s >= (ull)N || (ull)d >= (ull)N) return;
        int pos = atomicAdd(&g_deg[(int)d], 1);
        if (pos < MAXDEG) g_elist[(int)d * MAXDEG + pos] = (int)s;
    } else {
        int i = (blockIdx.x - buildBlocks) * blockDim.x + threadIdx.x;
        if (i >= NPAD * 32) return;
        int n = i >> 5, q = i & 31;
        float4 v = make_float4(0.f, 0.f, 0.f, 0.f);
        if (n < N) v = __ldg(reinterpret_cast<const float4*>(x) + (size_t)n * 32 + q);
        ((ull*)g_xh)[(size_t)n * 32 + q] = h4(v);
    }
}

// ---------------------------------------------------------------------------
// Kernel C: pull aggregation — one warp per node; fp32 accumulate; write
// mean as fp16. Covers NPAD so pad rows are zeroed.
// ---------------------------------------------------------------------------
__global__ void pull_kernel(const float* __restrict__ x, int N) {
    int node = blockIdx.x * (blockDim.x >> 5) + (threadIdx.x >> 5);
    if (node >= NPAD) return;
    int lane = threadIdx.x & 31;

    int deg = (node < N) ? g_deg[node] : 0;
    if (deg > MAXDEG) deg = MAXDEG;
    const int* lst = g_elist + (size_t)node * MAXDEG;
    const float4* x4 = reinterpret_cast<const float4*>(x);

    float4 acc = make_float4(0.f, 0.f, 0.f, 0.f);
    int j = 0;
    for (; j + 4 <= deg; j += 4) {
        int s0 = __ldg(lst + j),     s1 = __ldg(lst + j + 1);
        int s2 = __ldg(lst + j + 2), s3 = __ldg(lst + j + 3);
        float4 v0 = __ldg(&x4[(size_t)s0 * 32 + lane]);
        float4 v1 = __ldg(&x4[(size_t)s1 * 32 + lane]);
        float4 v2 = __ldg(&x4[(size_t)s2 * 32 + lane]);
        float4 v3 = __ldg(&x4[(size_t)s3 * 32 + lane]);
        acc.x += v0.x + v1.x + v2.x + v3.x;
        acc.y += v0.y + v1.y + v2.y + v3.y;
        acc.z += v0.z + v1.z + v2.z + v3.z;
        acc.w += v0.w + v1.w + v2.w + v3.w;
    }
    for (; j < deg; ++j) {
        int s0 = __ldg(lst + j);
        float4 v0 = __ldg(&x4[(size_t)s0 * 32 + lane]);
        acc.x += v0.x; acc.y += v0.y; acc.z += v0.z; acc.w += v0.w;
    }
    float inv = 1.f / fmaxf((float)deg, 1.f);
    acc.x *= inv; acc.y *= inv; acc.z *= inv; acc.w *= inv;
    ((ull*)g_mh)[(size_t)node * 32 + lane] = h4(acc);
}

// ---------------------------------------------------------------------------
// Kernel D: single-term fp16 mma.sync GEMM + bias + LayerNorm + ReLU.
// K=256 in 2 chunks of 128 (mean | x); tiles A,B only; smem 71KB -> 2 CTAs/SM.
// Per warp per k-step: 6 LDSM.x4 + 16 MMA (was 12 + 48 with 3-term bf16).
// ---------------------------------------------------------------------------
#define APITCH 272            // bytes per smem row (136 fp16); 17x16B, co-prime
#define S_A    0              // 128*272 = 34816
#define S_B    34816
#define S_BIAS 69632
#define S_GAM  70144
#define S_BET  70656
#define SMEM_TOT 71168
#define S_STAGE 0             // epilogue staging reuses tile region (67.6KB)
#define SPITCH 132

extern "C" __global__ void __launch_bounds__(256, 2)
gemm_mma_kernel(const float* __restrict__ bl,
                const float* __restrict__ gamma,
                const float* __restrict__ beta,
                float* __restrict__ out, int N) {
    extern __shared__ char dsm[];
    uint32_t sb = smem_u32(dsm);
    int tid = threadIdx.x;
    int w = tid >> 5, l = tid & 31;
    int wr = w >> 1, wc = w & 1;            // warp tile: rows wr*32, cols wc*64
    int row0 = blockIdx.x * 128;

    if (tid < 128) {
        ((float*)(dsm + S_BIAS))[tid] = bl[tid];
        ((float*)(dsm + S_GAM))[tid]  = gamma[tid];
        ((float*)(dsm + S_BET))[tid]  = beta[tid];
    }

    float acc[2][8][4];
#pragma unroll
    for (int a = 0; a < 2; ++a)
#pragma unroll
        for (int b = 0; b < 8; ++b)
#pragma unroll
            for (int c = 0; c < 4; ++c) acc[a][b][c] = 0.f;

    for (int kt = 0; kt < 2; ++kt) {                 // 2 chunks of K=128
        const __half* srcA = kt ? g_xh : g_mh;
        int kw = kt * 128;                           // k offset within W (256 wide)
        __syncthreads();

        // ---- A fill: 128 rows x 16 x 16B, pure cp.async ----
        for (int i = tid; i < 128 * 16; i += 256) {
            int r = i >> 4, q = i & 15;
            size_t gofs = (size_t)(row0 + r) * 128 + q * 8;
            cpa16(sb + S_A + r * APITCH + q * 16, srcA + gofs);
        }
        // ---- B fill: 128 n-rows x 16 x 16B ----
        for (int i = tid; i < 128 * 16; i += 256) {
            int n = i >> 4, q = i & 15;
            size_t gofs = (size_t)n * 256 + kw + q * 8;
            cpa16(sb + S_B + n * APITCH + q * 16, g_wh + gofs);
        }
        CPA_COMMIT();
        CPA_WAIT0();
        __syncthreads();

        // ---- compute: 8 k16 steps ----
#pragma unroll
        for (int ks = 0; ks < 8; ++ks) {
            int lrow = (l & 7) + (l & 8);
            int lcol = ks * 16 + ((l & 16) ? 8 : 0);
            uint32_t a[2][4];
#pragma unroll
            for (int mf = 0; mf < 2; ++mf) {
                int row = wr * 32 + mf * 16 + lrow;
                ldm4(a[mf], sb + S_A + row * APITCH + lcol * 2);
            }
#pragma unroll
            for (int nb = 0; nb < 4; ++nb) {
                int n = wc * 64 + nb * 16 + lrow;
                uint32_t b[4];
                ldm4(b, sb + S_B + n * APITCH + lcol * 2);
#pragma unroll
                for (int mf = 0; mf < 2; ++mf) {
                    mma16816(acc[mf][2 * nb],     a[mf], b[0], b[2]);
                    mma16816(acc[mf][2 * nb + 1], a[mf], b[1], b[3]);
                }
            }
        }
    }

    // ---- stage accumulators to smem (reuses tile region) ----
    __syncthreads();
    float* stag = (float*)(dsm + S_STAGE);
#pragma unroll
    for (int mf = 0; mf < 2; ++mf) {
#pragma unroll
        for (int nf = 0; nf < 8; ++nf) {
            int r = wr * 32 + mf * 16 + (l >> 2);
            int c = wc * 64 + nf * 8 + (l & 3) * 2;
            const float* cc = acc[mf][nf];
            *(float2*)(stag + r * SPITCH + c)       = make_float2(cc[0], cc[1]);
            *(float2*)(stag + (r + 8) * SPITCH + c) = make_float2(cc[2], cc[3]);
        }
    }
    __syncthreads();

    // ---- LN + ReLU: warp w handles rows w*16 .. w*16+15 ----
    const float4* biasS = (const float4*)(dsm + S_BIAS);
    const float4* gamS  = (const float4*)(dsm + S_GAM);
    const float4* betS  = (const float4*)(dsm + S_BET);
    float4 bb = biasS[l], gg = gamS[l], ee = betS[l];

    for (int r = w * 16; r < w * 16 + 16; ++r) {
        float4 v = *(const float4*)(stag + r * SPITCH + l * 4);
        v.x += bb.x; v.y += bb.y; v.z += bb.z; v.w += bb.w;
        float s = v.x + v.y + v.z + v.w;
#pragma unroll
        for (int m = 1; m < 32; m <<= 1) s += __shfl_xor_sync(0xffffffffu, s, m);
        float mu = s * (1.0f / 128.0f);
        float dx = v.x - mu, dy = v.y - mu, dz = v.z - mu, dw = v.w - mu;
        float q = dx * dx + dy * dy + dz * dz + dw * dw;
#pragma unroll
        for (int m = 1; m < 32; m <<= 1) q += __shfl_xor_sync(0xffffffffu, q, m);
        float rstd = rsqrtf(q * (1.0f / 128.0f) + 1e-5f);

        int g = row0 + r;
        if (g < N) {
            float4 o;
            o.x = fmaxf(fmaf(dx * rstd, gg.x, ee.x), 0.f);
            o.y = fmaxf(fmaf(dy * rstd, gg.y, ee.y), 0.f);
            o.z = fmaxf(fmaf(dz * rstd, gg.z, ee.z), 0.f);
            o.w = fmaxf(fmaf(dw * rstd, gg.w, ee.w), 0.f);
            *(float4*)(out + (size_t)g * 128 + l * 4) = o;
        }
    }
}

// ---------------------------------------------------------------------------
// Launch: prep, build+xprep (fused grid), pull, gemm.
// ---------------------------------------------------------------------------
extern "C" void kernel_launch(void* const* d_in, const int* in_sizes, int n_in,
                              void* d_out, int out_size) {
    const float* x      = (const float*)d_in[0];
    const void*  ei     = d_in[1];
    const float* Wl     = (const float*)d_in[2];
    const float* bl     = (const float*)d_in[3];
    const float* Wr     = (const float*)d_in[4];
    const float* gamma  = (const float*)d_in[5];
    const float* beta   = (const float*)d_in[6];
    float* out          = (float*)d_out;

    int N = in_sizes[0] / DIM;
    int E = in_sizes[1] / 2;

    cudaFuncSetAttribute(gemm_mma_kernel, cudaFuncAttributeMaxDynamicSharedMemorySize, SMEM_TOT);

    {
        int total = (N > 128 * 256) ? N : 128 * 256;
        prep_kernel<<<(total + 255) / 256, 256>>>(ei, E, N, Wl, Wr);
    }
    {
        int bb = BBLK(E);
        build_xprep_kernel<<<bb + XBLK, 256>>>(ei, x, E, N, bb);
    }
    {
        int blocks = (NPAD + 7) / 8;
        pull_kernel<<<blocks, 256>>>(x, N);
    }
    {
        int blocks = (N + 127) / 128;
        gemm_mma_kernel<<<blocks, 256, SMEM_TOT>>>(bl, gamma, beta, out, N);
    }
}

// round 15
// speedup vs baseline: 1.4125x; 1.0250x over previous
#include <cuda_runtime.h>
#include <cuda_fp16.h>
#include <cstdint>

#define DIM   128
#define MAXN  50000
#define NPAD  50176           // MAXN rounded up to multiple of 128 (pad rows)
#define MAXDEG 64
typedef unsigned long long ull;

// ---------------------------------------------------------------------------
// Device globals (no allocation allowed)
// ---------------------------------------------------------------------------
__device__ __align__(16) int    g_deg[MAXN];
__device__ __align__(16) int    g_elist[MAXN * MAXDEG];      // 12.8 MB
__device__ __align__(16) __half g_mh[NPAD * 128];            // mean, fp16
__device__ __align__(16) __half g_xh[NPAD * 128];            // x, fp16
__device__ __align__(16) __half g_wh[128 * 256];             // W_cat, fp16, [n][k]
__device__ int g_is64;

__device__ __forceinline__ uint32_t smem_u32(const void* p) {
    uint32_t a;
    asm("{ .reg .u64 t; cvta.to.shared.u64 t, %1; cvt.u32.u64 %0, t; }" : "=r"(a) : "l"(p));
    return a;
}
__device__ __forceinline__ void ldm4(uint32_t* r, uint32_t addr) {
    asm volatile("ldmatrix.sync.aligned.m8n8.x4.shared.b16 {%0,%1,%2,%3}, [%4];"
                 : "=r"(r[0]), "=r"(r[1]), "=r"(r[2]), "=r"(r[3]) : "r"(addr));
}
__device__ __forceinline__ void mma16816(float* c, const uint32_t* a, uint32_t b0, uint32_t b1) {
    asm volatile(
        "mma.sync.aligned.m16n8k16.row.col.f32.f16.f16.f32 "
        "{%0,%1,%2,%3}, {%4,%5,%6,%7}, {%8,%9}, {%0,%1,%2,%3};"
        : "+f"(c[0]), "+f"(c[1]), "+f"(c[2]), "+f"(c[3])
        : "r"(a[0]), "r"(a[1]), "r"(a[2]), "r"(a[3]), "r"(b0), "r"(b1));
}
__device__ __forceinline__ ull h4(float4 v) {
    __half2 a = __floats2half2_rn(v.x, v.y);
    __half2 b = __floats2half2_rn(v.z, v.w);
    return (ull)(*reinterpret_cast<uint32_t*>(&a)) |
           ((ull)(*reinterpret_cast<uint32_t*>(&b)) << 32);
}
__device__ __forceinline__ void unh4(ull v, float2& f0, float2& f1) {
    uint32_t lo = (uint32_t)v, hi = (uint32_t)(v >> 32);
    f0 = __half22float2(*reinterpret_cast<__half2*>(&lo));
    f1 = __half22float2(*reinterpret_cast<__half2*>(&hi));
}
__device__ __forceinline__ void cpa16(uint32_t smem, const void* g) {
    asm volatile("cp.async.ca.shared.global [%0], [%1], 16;" :: "r"(smem), "l"(g));
}
#define CPA_COMMIT() asm volatile("cp.async.commit_group;" ::: "memory")
#define CPA_WAIT0()  asm volatile("cp.async.wait_group 0;" ::: "memory")

// ---------------------------------------------------------------------------
// Kernel A (merged prep): detect dtype (block 0) + zero g_deg + W -> fp16.
// ---------------------------------------------------------------------------
__global__ void prep_kernel(const void* ei_raw, int E, int N,
                            const float* __restrict__ Wl, const float* __restrict__ Wr) {
    int i = blockIdx.x * blockDim.x + threadIdx.x;

    if (blockIdx.x == 0) {
        __shared__ int ok;
        if (threadIdx.x == 0) ok = 1;
        __syncthreads();
        const long long* e64 = (const long long*)ei_raw;
        int probe = (E < 1024) ? E : 1024;
        for (int j = threadIdx.x; j < probe; j += blockDim.x) {
            long long v = e64[j];
            if (v < 0 || v >= (long long)N) atomicExch(&ok, 0);
        }
        __syncthreads();
        if (threadIdx.x == 0) g_is64 = ok;
    }
    if (i < N) g_deg[i] = 0;
    if (i < 128 * 256) {
        int n = i >> 8, k = i & 255;
        float v = (k < 128) ? Wl[n * 128 + k] : Wr[n * 128 + (k - 128)];
        g_wh[i] = __float2half(v);
    }
}

// ---------------------------------------------------------------------------
// Kernel B (merged): build edge lists + x -> fp16 (grid-split fusion)
// ---------------------------------------------------------------------------
#define BBLK(E) (((E) + 255) / 256)
#define XBLK    ((NPAD * 32 + 255) / 256)

__global__ void build_xprep_kernel(const void* __restrict__ ei_raw,
                                   const float* __restrict__ x, int E, int N,
                                   int buildBlocks) {
    if ((int)blockIdx.x < buildBlocks) {
        int e = blockIdx.x * blockDim.x + threadIdx.x;
        if (e >= E) return;
        long long s, d;
        if (g_is64) {
            const long long* ei = (const long long*)ei_raw;
            s = __ldg(&ei[e]);  d = __ldg(&ei[E + e]);
        } else {
            const int* ei = (const int*)ei_raw;
            s = __ldg(&ei[e]);  d = __ldg(&ei[E + e]);
        }
        if ((ull)s >= (ull)N || (ull)d >= (ull)N) return;
        int pos = atomicAdd(&g_deg[(int)d], 1);
        if (pos < MAXDEG) g_elist[(int)d * MAXDEG + pos] = (int)s;
    } else {
        int i = (blockIdx.x - buildBlocks) * blockDim.x + threadIdx.x;
        if (i >= NPAD * 32) return;
        int n = i >> 5, q = i & 31;
        float4 v = make_float4(0.f, 0.f, 0.f, 0.f);
        if (n < N) v = __ldg(reinterpret_cast<const float4*>(x) + (size_t)n * 32 + q);
        ((ull*)g_xh)[(size_t)n * 32 + q] = h4(v);
    }
}

// ---------------------------------------------------------------------------
// Kernel C: pull aggregation — one warp per node, gathering FP16 rows
// (256B/row: half the LTS traffic of fp32). fp32 accumulate; fp16 mean out.
// ---------------------------------------------------------------------------
__global__ void pull_kernel(int N) {
    int node = blockIdx.x * (blockDim.x >> 5) + (threadIdx.x >> 5);
    if (node >= NPAD) return;
    int lane = threadIdx.x & 31;

    int deg = (node < N) ? g_deg[node] : 0;
    if (deg > MAXDEG) deg = MAXDEG;
    const int* lst = g_elist + (size_t)node * MAXDEG;
    const ull* xh = reinterpret_cast<const ull*>(g_xh);

    float4 acc = make_float4(0.f, 0.f, 0.f, 0.f);
    int j = 0;
    for (; j + 4 <= deg; j += 4) {
        int s0 = __ldg(lst + j),     s1 = __ldg(lst + j + 1);
        int s2 = __ldg(lst + j + 2), s3 = __ldg(lst + j + 3);
        ull v0 = __ldg(&xh[(size_t)s0 * 32 + lane]);
        ull v1 = __ldg(&xh[(size_t)s1 * 32 + lane]);
        ull v2 = __ldg(&xh[(size_t)s2 * 32 + lane]);
        ull v3 = __ldg(&xh[(size_t)s3 * 32 + lane]);
        float2 a0, a1, b0, b1, c0, c1, d0, d1;
        unh4(v0, a0, a1); unh4(v1, b0, b1); unh4(v2, c0, c1); unh4(v3, d0, d1);
        acc.x += a0.x + b0.x + c0.x + d0.x;
        acc.y += a0.y + b0.y + c0.y + d0.y;
        acc.z += a1.x + b1.x + c1.x + d1.x;
        acc.w += a1.y + b1.y + c1.y + d1.y;
    }
    for (; j < deg; ++j) {
        int s0 = __ldg(lst + j);
        ull v0 = __ldg(&xh[(size_t)s0 * 32 + lane]);
        float2 a0, a1;
        unh4(v0, a0, a1);
        acc.x += a0.x; acc.y += a0.y; acc.z += a1.x; acc.w += a1.y;
    }
    float inv = 1.f / fmaxf((float)deg, 1.f);
    acc.x *= inv; acc.y *= inv; acc.z *= inv; acc.w *= inv;
    ((ull*)g_mh)[(size_t)node * 32 + lane] = h4(acc);
}

// ---------------------------------------------------------------------------
// Kernel D: single-term fp16 mma.sync GEMM + bias + LayerNorm + ReLU.
// K=256 in 2 chunks of 128 (mean | x); smem 71KB; __launch_bounds__(256,3)
// -> 3 CTAs/SM: 391 CTAs fit in ONE wave (444 slots) + more latency hiding.
// ---------------------------------------------------------------------------
#define APITCH 272            // bytes per smem row (136 fp16); 17x16B, co-prime
#define S_A    0              // 128*272 = 34816
#define S_B    34816
#define S_BIAS 69632
#define S_GAM  70144
#define S_BET  70656
#define SMEM_TOT 71168
#define S_STAGE 0             // epilogue staging reuses tile region (67.6KB)
#define SPITCH 132

extern "C" __global__ void __launch_bounds__(256, 3)
gemm_mma_kernel(const float* __restrict__ bl,
                const float* __restrict__ gamma,
                const float* __restrict__ beta,
                float* __restrict__ out, int N) {
    extern __shared__ char dsm[];
    uint32_t sb = smem_u32(dsm);
    int tid = threadIdx.x;
    int w = tid >> 5, l = tid & 31;
    int wr = w >> 1, wc = w & 1;            // warp tile: rows wr*32, cols wc*64
    int row0 = blockIdx.x * 128;

    if (tid < 128) {
        ((float*)(dsm + S_BIAS))[tid] = bl[tid];
        ((float*)(dsm + S_GAM))[tid]  = gamma[tid];
        ((float*)(dsm + S_BET))[tid]  = beta[tid];
    }

    float acc[2][8][4];
#pragma unroll
    for (int a = 0; a < 2; ++a)
#pragma unroll
        for (int b = 0; b < 8; ++b)
#pragma unroll
            for (int c = 0; c < 4; ++c) acc[a][b][c] = 0.f;

    for (int kt = 0; kt < 2; ++kt) {                 // 2 chunks of K=128
        const __half* srcA = kt ? g_xh : g_mh;
        int kw = kt * 128;                           // k offset within W (256 wide)
        __syncthreads();

        // ---- A fill: 128 rows x 16 x 16B, pure cp.async ----
        for (int i = tid; i < 128 * 16; i += 256) {
            int r = i >> 4, q = i & 15;
            size_t gofs = (size_t)(row0 + r) * 128 + q * 8;
            cpa16(sb + S_A + r * APITCH + q * 16, srcA + gofs);
        }
        // ---- B fill: 128 n-rows x 16 x 16B ----
        for (int i = tid; i < 128 * 16; i += 256) {
            int n = i >> 4, q = i & 15;
            size_t gofs = (size_t)n * 256 + kw + q * 8;
            cpa16(sb + S_B + n * APITCH + q * 16, g_wh + gofs);
        }
        CPA_COMMIT();
        CPA_WAIT0();
        __syncthreads();

        // ---- compute: 8 k16 steps ----
#pragma unroll
        for (int ks = 0; ks < 8; ++ks) {
            int lrow = (l & 7) + (l & 8);
            int lcol = ks * 16 + ((l & 16) ? 8 : 0);
            uint32_t a[2][4];
#pragma unroll
            for (int mf = 0; mf < 2; ++mf) {
                int row = wr * 32 + mf * 16 + lrow;
                ldm4(a[mf], sb + S_A + row * APITCH + lcol * 2);
            }
#pragma unroll
            for (int nb = 0; nb < 4; ++nb) {
                int n = wc * 64 + nb * 16 + lrow;
                uint32_t b[4];
                ldm4(b, sb + S_B + n * APITCH + lcol * 2);
#pragma unroll
                for (int mf = 0; mf < 2; ++mf) {
                    mma16816(acc[mf][2 * nb],     a[mf], b[0], b[2]);
                    mma16816(acc[mf][2 * nb + 1], a[mf], b[1], b[3]);
                }
            }
        }
    }

    // ---- stage accumulators to smem (reuses tile region) ----
    __syncthreads();
    float* stag = (float*)(dsm + S_STAGE);
#pragma unroll
    for (int mf = 0; mf < 2; ++mf) {
#pragma unroll
        for (int nf = 0; nf < 8; ++nf) {
            int r = wr * 32 + mf * 16 + (l >> 2);
            int c = wc * 64 + nf * 8 + (l & 3) * 2;
            const float* cc = acc[mf][nf];
            *(float2*)(stag + r * SPITCH + c)       = make_float2(cc[0], cc[1]);
            *(float2*)(stag + (r + 8) * SPITCH + c) = make_float2(cc[2], cc[3]);
        }
    }
    __syncthreads();

    // ---- LN + ReLU: warp w handles rows w*16 .. w*16+15 ----
    const float4* biasS = (const float4*)(dsm + S_BIAS);
    const float4* gamS  = (const float4*)(dsm + S_GAM);
    const float4* betS  = (const float4*)(dsm + S_BET);
    float4 bb = biasS[l], gg = gamS[l], ee = betS[l];

    for (int r = w * 16; r < w * 16 + 16; ++r) {
        float4 v = *(const float4*)(stag + r * SPITCH + l * 4);
        v.x += bb.x; v.y += bb.y; v.z += bb.z; v.w += bb.w;
        float s = v.x + v.y + v.z + v.w;
#pragma unroll
        for (int m = 1; m < 32; m <<= 1) s += __shfl_xor_sync(0xffffffffu, s, m);
        float mu = s * (1.0f / 128.0f);
        float dx = v.x - mu, dy = v.y - mu, dz = v.z - mu, dw = v.w - mu;
        float q = dx * dx + dy * dy + dz * dz + dw * dw;
#pragma unroll
        for (int m = 1; m < 32; m <<= 1) q += __shfl_xor_sync(0xffffffffu, q, m);
        float rstd = rsqrtf(q * (1.0f / 128.0f) + 1e-5f);

        int g = row0 + r;
        if (g < N) {
            float4 o;
            o.x = fmaxf(fmaf(dx * rstd, gg.x, ee.x), 0.f);
            o.y = fmaxf(fmaf(dy * rstd, gg.y, ee.y), 0.f);
            o.z = fmaxf(fmaf(dz * rstd, gg.z, ee.z), 0.f);
            o.w = fmaxf(fmaf(dw * rstd, gg.w, ee.w), 0.f);
            *(float4*)(out + (size_t)g * 128 + l * 4) = o;
        }
    }
}

// ---------------------------------------------------------------------------
// Launch: prep, build+xprep (fused grid), pull, gemm.
// ---------------------------------------------------------------------------
extern "C" void kernel_launch(void* const* d_in, const int* in_sizes, int n_in,
                              void* d_out, int out_size) {
    const float* x      = (const float*)d_in[0];
    const void*  ei     = d_in[1];
    const float* Wl     = (const float*)d_in[2];
    const float* bl     = (const float*)d_in[3];
    const float* Wr     = (const float*)d_in[4];
    const float* gamma  = (const float*)d_in[5];
    const float* beta   = (const float*)d_in[6];
    float* out          = (float*)d_out;

    int N = in_sizes[0] / DIM;
    int E = in_sizes[1] / 2;

    cudaFuncSetAttribute(gemm_mma_kernel, cudaFuncAttributeMaxDynamicSharedMemorySize, SMEM_TOT);

    {
        int total = (N > 128 * 256) ? N : 128 * 256;
        prep_kernel<<<(total + 255) / 256, 256>>>(ei, E, N, Wl, Wr);
    }
    {
        int bb = BBLK(E);
        build_xprep_kernel<<<bb + XBLK, 256>>>(ei, x, E, N, bb);
    }
    {
        int blocks = (NPAD + 7) / 8;
        pull_kernel<<<blocks, 256>>>(N);
    }
    {
        int blocks = (N + 127) / 128;
        gemm_mma_kernel<<<blocks, 256, SMEM_TOT>>>(bl, gamma, beta, out, N);
    }
}

// round 16
// speedup vs baseline: 1.4971x; 1.0599x over previous
#include <cuda_runtime.h>
#include <cuda_fp16.h>
#include <cstdint>

#define DIM   128
#define MAXN  50000
#define NPAD  50176           // MAXN rounded up to multiple of 128 (pad rows)
#define MAXDEG 64
typedef unsigned long long ull;

// ---------------------------------------------------------------------------
// Device globals (no allocation allowed)
// ---------------------------------------------------------------------------
__device__ __align__(16) int    g_deg[MAXN];
__device__ __align__(16) int    g_elist[MAXN * MAXDEG];      // 12.8 MB
__device__ __align__(16) __half g_mh[NPAD * 128];            // mean, fp16
__device__ __align__(16) __half g_xh[NPAD * 128];            // x, fp16
__device__ __align__(16) __half g_wh[128 * 256];             // W_cat, fp16, [n][k]
__device__ int g_is64;

__device__ __forceinline__ uint32_t smem_u32(const void* p) {
    uint32_t a;
    asm("{ .reg .u64 t; cvta.to.shared.u64 t, %1; cvt.u32.u64 %0, t; }" : "=r"(a) : "l"(p));
    return a;
}
__device__ __forceinline__ void ldm4(uint32_t* r, uint32_t addr) {
    asm volatile("ldmatrix.sync.aligned.m8n8.x4.shared.b16 {%0,%1,%2,%3}, [%4];"
                 : "=r"(r[0]), "=r"(r[1]), "=r"(r[2]), "=r"(r[3]) : "r"(addr));
}
__device__ __forceinline__ void mma16816(float* c, const uint32_t* a, uint32_t b0, uint32_t b1) {
    asm volatile(
        "mma.sync.aligned.m16n8k16.row.col.f32.f16.f16.f32 "
        "{%0,%1,%2,%3}, {%4,%5,%6,%7}, {%8,%9}, {%0,%1,%2,%3};"
        : "+f"(c[0]), "+f"(c[1]), "+f"(c[2]), "+f"(c[3])
        : "r"(a[0]), "r"(a[1]), "r"(a[2]), "r"(a[3]), "r"(b0), "r"(b1));
}
__device__ __forceinline__ ull h4(float4 v) {
    __half2 a = __floats2half2_rn(v.x, v.y);
    __half2 b = __floats2half2_rn(v.z, v.w);
    return (ull)(*reinterpret_cast<uint32_t*>(&a)) |
           ((ull)(*reinterpret_cast<uint32_t*>(&b)) << 32);
}
__device__ __forceinline__ void unh4(ull v, float2& f0, float2& f1) {
    uint32_t lo = (uint32_t)v, hi = (uint32_t)(v >> 32);
    f0 = __half22float2(*reinterpret_cast<__half2*>(&lo));
    f1 = __half22float2(*reinterpret_cast<__half2*>(&hi));
}
__device__ __forceinline__ void cpa16(uint32_t smem, const void* g) {
    asm volatile("cp.async.ca.shared.global [%0], [%1], 16;" :: "r"(smem), "l"(g));
}
#define CPA_COMMIT() asm volatile("cp.async.commit_group;" ::: "memory")
#define CPA_WAIT0()  asm volatile("cp.async.wait_group 0;" ::: "memory")

// ---------------------------------------------------------------------------
// Kernel A (merged prep): detect dtype (block 0) + zero g_deg + W -> fp16.
// ---------------------------------------------------------------------------
__global__ void prep_kernel(const void* ei_raw, int E, int N,
                            const float* __restrict__ Wl, const float* __restrict__ Wr) {
    int i = blockIdx.x * blockDim.x + threadIdx.x;

    if (blockIdx.x == 0) {
        __shared__ int ok;
        if (threadIdx.x == 0) ok = 1;
        __syncthreads();
        const long long* e64 = (const long long*)ei_raw;
        int probe = (E < 1024) ? E : 1024;
        for (int j = threadIdx.x; j < probe; j += blockDim.x) {
            long long v = e64[j];
            if (v < 0 || v >= (long long)N) atomicExch(&ok, 0);
        }
        __syncthreads();
        if (threadIdx.x == 0) g_is64 = ok;
    }
    if (i < N) g_deg[i] = 0;
    if (i < 128 * 256) {
        int n = i >> 8, k = i & 255;
        float v = (k < 128) ? Wl[n * 128 + k] : Wr[n * 128 + (k - 128)];
        g_wh[i] = __float2half(v);
    }
}

// ---------------------------------------------------------------------------
// Kernel B (merged): build edge lists + x -> fp16 (grid-split fusion)
// ---------------------------------------------------------------------------
#define BBLK(E) (((E) + 255) / 256)
#define XBLK    ((NPAD * 32 + 255) / 256)

__global__ void build_xprep_kernel(const void* __restrict__ ei_raw,
                                   const float* __restrict__ x, int E, int N,
                                   int buildBlocks) {
    if ((int)blockIdx.x < buildBlocks) {
        int e = blockIdx.x * blockDim.x + threadIdx.x;
        if (e >= E) return;
        long long s, d;
        if (g_is64) {
            const long long* ei = (const long long*)ei_raw;
            s = __ldg(&ei[e]);  d = __ldg(&ei[E + e]);
        } else {
            const int* ei = (const int*)ei_raw;
            s = __ldg(&ei[e]);  d = __ldg(&ei[E + e]);
        }
        if ((ull)s >= (ull)N || (ull)d >= (ull)N) return;
        int pos = atomicAdd(&g_deg[(int)d], 1);
        if (pos < MAXDEG) g_elist[(int)d * MAXDEG + pos] = (int)s;
    } else {
        int i = (blockIdx.x - buildBlocks) * blockDim.x + threadIdx.x;
        if (i >= NPAD * 32) return;
        int n = i >> 5, q = i & 31;
        float4 v = make_float4(0.f, 0.f, 0.f, 0.f);
        if (n < N) v = __ldg(reinterpret_cast<const float4*>(x) + (size_t)n * 32 + q);
        ((ull*)g_xh)[(size_t)n * 32 + q] = h4(v);
    }
}

// ---------------------------------------------------------------------------
// Kernel C: pull aggregation — one warp per node, gathering FP16 rows
// (256B/row: half the LTS traffic of fp32). fp32 accumulate; fp16 mean out.
// ---------------------------------------------------------------------------
__global__ void pull_kernel(int N) {
    int node = blockIdx.x * (blockDim.x >> 5) + (threadIdx.x >> 5);
    if (node >= NPAD) return;
    int lane = threadIdx.x & 31;

    int deg = (node < N) ? g_deg[node] : 0;
    if (deg > MAXDEG) deg = MAXDEG;
    const int* lst = g_elist + (size_t)node * MAXDEG;
    const ull* xh = reinterpret_cast<const ull*>(g_xh);

    float4 acc = make_float4(0.f, 0.f, 0.f, 0.f);
    int j = 0;
    for (; j + 4 <= deg; j += 4) {
        int s0 = __ldg(lst + j),     s1 = __ldg(lst + j + 1);
        int s2 = __ldg(lst + j + 2), s3 = __ldg(lst + j + 3);
        ull v0 = __ldg(&xh[(size_t)s0 * 32 + lane]);
        ull v1 = __ldg(&xh[(size_t)s1 * 32 + lane]);
        ull v2 = __ldg(&xh[(size_t)s2 * 32 + lane]);
        ull v3 = __ldg(&xh[(size_t)s3 * 32 + lane]);
        float2 a0, a1, b0, b1, c0, c1, d0, d1;
        unh4(v0, a0, a1); unh4(v1, b0, b1); unh4(v2, c0, c1); unh4(v3, d0, d1);
        acc.x += a0.x + b0.x + c0.x + d0.x;
        acc.y += a0.y + b0.y + c0.y + d0.y;
        acc.z += a1.x + b1.x + c1.x + d1.x;
        acc.w += a1.y + b1.y + c1.y + d1.y;
    }
    for (; j < deg; ++j) {
        int s0 = __ldg(lst + j);
        ull v0 = __ldg(&xh[(size_t)s0 * 32 + lane]);
        float2 a0, a1;
        unh4(v0, a0, a1);
        acc.x += a0.x; acc.y += a0.y; acc.z += a1.x; acc.w += a1.y;
    }
    float inv = 1.f / fmaxf((float)deg, 1.f);
    acc.x *= inv; acc.y *= inv; acc.z *= inv; acc.w *= inv;
    ((ull*)g_mh)[(size_t)node * 32 + lane] = h4(acc);
}

// ---------------------------------------------------------------------------
// Kernel D: single-term fp16 mma.sync GEMM + bias + LayerNorm + ReLU.
// K=256 in 2 chunks of 128 (mean | x); smem 71KB -> 2 CTAs/SM.
// __launch_bounds__(256,2): the 3-CTA variant forced 80 regs and spilled
// (GEMM 26.2 -> 32.9us); 112 regs at 2 CTAs/SM is the proven optimum.
// ---------------------------------------------------------------------------
#define APITCH 272            // bytes per smem row (136 fp16); 17x16B, co-prime
#define S_A    0              // 128*272 = 34816
#define S_B    34816
#define S_BIAS 69632
#define S_GAM  70144
#define S_BET  70656
#define SMEM_TOT 71168
#define S_STAGE 0             // epilogue staging reuses tile region (67.6KB)
#define SPITCH 132

extern "C" __global__ void __launch_bounds__(256, 2)
gemm_mma_kernel(const float* __restrict__ bl,
                const float* __restrict__ gamma,
                const float* __restrict__ beta,
                float* __restrict__ out, int N) {
    extern __shared__ char dsm[];
    uint32_t sb = smem_u32(dsm);
    int tid = threadIdx.x;
    int w = tid >> 5, l = tid & 31;
    int wr = w >> 1, wc = w & 1;            // warp tile: rows wr*32, cols wc*64
    int row0 = blockIdx.x * 128;

    if (tid < 128) {
        ((float*)(dsm + S_BIAS))[tid] = bl[tid];
        ((float*)(dsm + S_GAM))[tid]  = gamma[tid];
        ((float*)(dsm + S_BET))[tid]  = beta[tid];
    }

    float acc[2][8][4];
#pragma unroll
    for (int a = 0; a < 2; ++a)
#pragma unroll
        for (int b = 0; b < 8; ++b)
#pragma unroll
            for (int c = 0; c < 4; ++c) acc[a][b][c] = 0.f;

    for (int kt = 0; kt < 2; ++kt) {                 // 2 chunks of K=128
        const __half* srcA = kt ? g_xh : g_mh;
        int kw = kt * 128;                           // k offset within W (256 wide)
        __syncthreads();

        // ---- A fill: 128 rows x 16 x 16B, pure cp.async ----
        for (int i = tid; i < 128 * 16; i += 256) {
            int r = i >> 4, q = i & 15;
            size_t gofs = (size_t)(row0 + r) * 128 + q * 8;
            cpa16(sb + S_A + r * APITCH + q * 16, srcA + gofs);
        }
        // ---- B fill: 128 n-rows x 16 x 16B ----
        for (int i = tid; i < 128 * 16; i += 256) {
            int n = i >> 4, q = i & 15;
            size_t gofs = (size_t)n * 256 + kw + q * 8;
            cpa16(sb + S_B + n * APITCH + q * 16, g_wh + gofs);
        }
        CPA_COMMIT();
        CPA_WAIT0();
        __syncthreads();

        // ---- compute: 8 k16 steps ----
#pragma unroll
        for (int ks = 0; ks < 8; ++ks) {
            int lrow = (l & 7) + (l & 8);
            int lcol = ks * 16 + ((l & 16) ? 8 : 0);
            uint32_t a[2][4];
#pragma unroll
            for (int mf = 0; mf < 2; ++mf) {
                int row = wr * 32 + mf * 16 + lrow;
                ldm4(a[mf], sb + S_A + row * APITCH + lcol * 2);
            }
#pragma unroll
            for (int nb = 0; nb < 4; ++nb) {
                int n = wc * 64 + nb * 16 + lrow;
                uint32_t b[4];
                ldm4(b, sb + S_B + n * APITCH + lcol * 2);
#pragma unroll
                for (int mf = 0; mf < 2; ++mf) {
                    mma16816(acc[mf][2 * nb],     a[mf], b[0], b[2]);
                    mma16816(acc[mf][2 * nb + 1], a[mf], b[1], b[3]);
                }
            }
        }
    }

    // ---- stage accumulators to smem (reuses tile region) ----
    __syncthreads();
    float* stag = (float*)(dsm + S_STAGE);
#pragma unroll
    for (int mf = 0; mf < 2; ++mf) {
#pragma unroll
        for (int nf = 0; nf < 8; ++nf) {
            int r = wr * 32 + mf * 16 + (l >> 2);
            int c = wc * 64 + nf * 8 + (l & 3) * 2;
            const float* cc = acc[mf][nf];
            *(float2*)(stag + r * SPITCH + c)       = make_float2(cc[0], cc[1]);
            *(float2*)(stag + (r + 8) * SPITCH + c) = make_float2(cc[2], cc[3]);
        }
    }
    __syncthreads();

    // ---- LN + ReLU: warp w handles rows w*16 .. w*16+15 ----
    const float4* biasS = (const float4*)(dsm + S_BIAS);
    const float4* gamS  = (const float4*)(dsm + S_GAM);
    const float4* betS  = (const float4*)(dsm + S_BET);
    float4 bb = biasS[l], gg = gamS[l], ee = betS[l];

    for (int r = w * 16; r < w * 16 + 16; ++r) {
        float4 v = *(const float4*)(stag + r * SPITCH + l * 4);
        v.x += bb.x; v.y += bb.y; v.z += bb.z; v.w += bb.w;
        float s = v.x + v.y + v.z + v.w;
#pragma unroll
        for (int m = 1; m < 32; m <<= 1) s += __shfl_xor_sync(0xffffffffu, s, m);
        float mu = s * (1.0f / 128.0f);
        float dx = v.x - mu, dy = v.y - mu, dz = v.z - mu, dw = v.w - mu;
        float q = dx * dx + dy * dy + dz * dz + dw * dw;
#pragma unroll
        for (int m = 1; m < 32; m <<= 1) q += __shfl_xor_sync(0xffffffffu, q, m);
        float rstd = rsqrtf(q * (1.0f / 128.0f) + 1e-5f);

        int g = row0 + r;
        if (g < N) {
            float4 o;
            o.x = fmaxf(fmaf(dx * rstd, gg.x, ee.x), 0.f);
            o.y = fmaxf(fmaf(dy * rstd, gg.y, ee.y), 0.f);
            o.z = fmaxf(fmaf(dz * rstd, gg.z, ee.z), 0.f);
            o.w = fmaxf(fmaf(dw * rstd, gg.w, ee.w), 0.f);
            *(float4*)(out + (size_t)g * 128 + l * 4) = o;
        }
    }
}

// ---------------------------------------------------------------------------
// Launch: prep, build+xprep (fused grid), pull, gemm.
// ---------------------------------------------------------------------------
extern "C" void kernel_launch(void* const* d_in, const int* in_sizes, int n_in,
                              void* d_out, int out_size) {
    const float* x      = (const float*)d_in[0];
    const void*  ei     = d_in[1];
    const float* Wl     = (const float*)d_in[2];
    const float* bl     = (const float*)d_in[3];
    const float* Wr     = (const float*)d_in[4];
    const float* gamma  = (const float*)d_in[5];
    const float* beta   = (const float*)d_in[6];
    float* out          = (float*)d_out;

    int N = in_sizes[0] / DIM;
    int E = in_sizes[1] / 2;

    cudaFuncSetAttribute(gemm_mma_kernel, cudaFuncAttributeMaxDynamicSharedMemorySize, SMEM_TOT);

    {
        int total = (N > 128 * 256) ? N : 128 * 256;
        prep_kernel<<<(total + 255) / 256, 256>>>(ei, E, N, Wl, Wr);
    }
    {
        int bb = BBLK(E);
        build_xprep_kernel<<<bb + XBLK, 256>>>(ei, x, E, N, bb);
    }
    {
        int blocks = (NPAD + 7) / 8;
        pull_kernel<<<blocks, 256>>>(N);
    }
    {
        int blocks = (N + 127) / 128;
        gemm_mma_kernel<<<blocks, 256, SMEM_TOT>>>(bl, gamma, beta, out, N);
    }
}

// round 17
// speedup vs baseline: 1.5634x; 1.0443x over previous
#include <cuda_runtime.h>
#include <cuda_fp16.h>
#include <cstdint>

#define DIM   128
#define MAXN  50000
#define NPAD  50176           // MAXN rounded up to multiple of 128 (pad rows)
#define MAXDEG 64
typedef unsigned long long ull;

// ---------------------------------------------------------------------------
// Device globals (no allocation allowed)
// ---------------------------------------------------------------------------
__device__ __align__(16) int    g_deg[MAXN];
__device__ __align__(16) int    g_elist[MAXN * MAXDEG];      // 12.8 MB
__device__ __align__(16) __half g_mh[NPAD * 128];            // mean, fp16
__device__ __align__(16) __half g_xh[NPAD * 128];            // x, fp16
__device__ __align__(16) __half g_wh[128 * 256];             // W_cat, fp16, [n][k]
__device__ int g_is64;

__device__ __forceinline__ uint32_t smem_u32(const void* p) {
    uint32_t a;
    asm("{ .reg .u64 t; cvta.to.shared.u64 t, %1; cvt.u32.u64 %0, t; }" : "=r"(a) : "l"(p));
    return a;
}
__device__ __forceinline__ void ldm4(uint32_t* r, uint32_t addr) {
    asm volatile("ldmatrix.sync.aligned.m8n8.x4.shared.b16 {%0,%1,%2,%3}, [%4];"
                 : "=r"(r[0]), "=r"(r[1]), "=r"(r[2]), "=r"(r[3]) : "r"(addr));
}
__device__ __forceinline__ void mma16816(float* c, const uint32_t* a, uint32_t b0, uint32_t b1) {
    asm volatile(
        "mma.sync.aligned.m16n8k16.row.col.f32.f16.f16.f32 "
        "{%0,%1,%2,%3}, {%4,%5,%6,%7}, {%8,%9}, {%0,%1,%2,%3};"
        : "+f"(c[0]), "+f"(c[1]), "+f"(c[2]), "+f"(c[3])
        : "r"(a[0]), "r"(a[1]), "r"(a[2]), "r"(a[3]), "r"(b0), "r"(b1));
}
__device__ __forceinline__ ull h4(float4 v) {
    __half2 a = __floats2half2_rn(v.x, v.y);
    __half2 b = __floats2half2_rn(v.z, v.w);
    return (ull)(*reinterpret_cast<uint32_t*>(&a)) |
           ((ull)(*reinterpret_cast<uint32_t*>(&b)) << 32);
}
__device__ __forceinline__ void unh4(ull v, float2& f0, float2& f1) {
    uint32_t lo = (uint32_t)v, hi = (uint32_t)(v >> 32);
    f0 = __half22float2(*reinterpret_cast<__half2*>(&lo));
    f1 = __half22float2(*reinterpret_cast<__half2*>(&hi));
}
__device__ __forceinline__ void cpa16(uint32_t smem, const void* g) {
    asm volatile("cp.async.ca.shared.global [%0], [%1], 16;" :: "r"(smem), "l"(g));
}
#define CPA_COMMIT() asm volatile("cp.async.commit_group;" ::: "memory")
#define CPA_WAIT0()  asm volatile("cp.async.wait_group 0;" ::: "memory")

// ---------------------------------------------------------------------------
// Kernel A (merged prep): detect dtype (block 0) + zero g_deg + W -> fp16.
// ---------------------------------------------------------------------------
__global__ void prep_kernel(const void* ei_raw, int E, int N,
                            const float* __restrict__ Wl, const float* __restrict__ Wr) {
    int i = blockIdx.x * blockDim.x + threadIdx.x;

    if (blockIdx.x == 0) {
        __shared__ int ok;
        if (threadIdx.x == 0) ok = 1;
        __syncthreads();
        const long long* e64 = (const long long*)ei_raw;
        int probe = (E < 1024) ? E : 1024;
        for (int j = threadIdx.x; j < probe; j += blockDim.x) {
            long long v = e64[j];
            if (v < 0 || v >= (long long)N) atomicExch(&ok, 0);
        }
        __syncthreads();
        if (threadIdx.x == 0) g_is64 = ok;
    }
    if (i < N) g_deg[i] = 0;
    if (i < 128 * 256) {
        int n = i >> 8, k = i & 255;
        float v = (k < 128) ? Wl[n * 128 + k] : Wr[n * 128 + (k - 128)];
        g_wh[i] = __float2half(v);
    }
}

// ---------------------------------------------------------------------------
// Kernel B (merged): build edge lists + x -> fp16 (grid-split fusion)
// ---------------------------------------------------------------------------
#define BBLK(E) (((E) + 255) / 256)
#define XBLK    ((NPAD * 32 + 255) / 256)

__global__ void build_xprep_kernel(const void* __restrict__ ei_raw,
                                   const float* __restrict__ x, int E, int N,
                                   int buildBlocks) {
    if ((int)blockIdx.x < buildBlocks) {
        int e = blockIdx.x * blockDim.x + threadIdx.x;
        if (e >= E) return;
        long long s, d;
        if (g_is64) {
            const long long* ei = (const long long*)ei_raw;
            s = __ldg(&ei[e]);  d = __ldg(&ei[E + e]);
        } else {
            const int* ei = (const int*)ei_raw;
            s = __ldg(&ei[e]);  d = __ldg(&ei[E + e]);
        }
        if ((ull)s >= (ull)N || (ull)d >= (ull)N) return;
        int pos = atomicAdd(&g_deg[(int)d], 1);
        if (pos < MAXDEG) g_elist[(int)d * MAXDEG + pos] = (int)s;
    } else {
        int i = (blockIdx.x - buildBlocks) * blockDim.x + threadIdx.x;
        if (i >= NPAD * 32) return;
        int n = i >> 5, q = i & 31;
        float4 v = make_float4(0.f, 0.f, 0.f, 0.f);
        if (n < N) v = __ldg(reinterpret_cast<const float4*>(x) + (size_t)n * 32 + q);
        ((ull*)g_xh)[(size_t)n * 32 + q] = h4(v);
    }
}

// ---------------------------------------------------------------------------
// Kernel C: pull aggregation — one warp per node, gathering FP16 rows.
// fp32 accumulate; fp16 mean out. Covers NPAD so pad rows are zeroed.
// ---------------------------------------------------------------------------
__global__ void pull_kernel(int N) {
    int node = blockIdx.x * (blockDim.x >> 5) + (threadIdx.x >> 5);
    if (node >= NPAD) return;
    int lane = threadIdx.x & 31;

    int deg = (node < N) ? g_deg[node] : 0;
    if (deg > MAXDEG) deg = MAXDEG;
    const int* lst = g_elist + (size_t)node * MAXDEG;
    const ull* xh = reinterpret_cast<const ull*>(g_xh);

    float4 acc = make_float4(0.f, 0.f, 0.f, 0.f);
    int j = 0;
    for (; j + 4 <= deg; j += 4) {
        int s0 = __ldg(lst + j),     s1 = __ldg(lst + j + 1);
        int s2 = __ldg(lst + j + 2), s3 = __ldg(lst + j + 3);
        ull v0 = __ldg(&xh[(size_t)s0 * 32 + lane]);
        ull v1 = __ldg(&xh[(size_t)s1 * 32 + lane]);
        ull v2 = __ldg(&xh[(size_t)s2 * 32 + lane]);
        ull v3 = __ldg(&xh[(size_t)s3 * 32 + lane]);
        float2 a0, a1, b0, b1, c0, c1, d0, d1;
        unh4(v0, a0, a1); unh4(v1, b0, b1); unh4(v2, c0, c1); unh4(v3, d0, d1);
        acc.x += a0.x + b0.x + c0.x + d0.x;
        acc.y += a0.y + b0.y + c0.y + d0.y;
        acc.z += a1.x + b1.x + c1.x + d1.x;
        acc.w += a1.y + b1.y + c1.y + d1.y;
    }
    for (; j < deg; ++j) {
        int s0 = __ldg(lst + j);
        ull v0 = __ldg(&xh[(size_t)s0 * 32 + lane]);
        float2 a0, a1;
        unh4(v0, a0, a1);
        acc.x += a0.x; acc.y += a0.y; acc.z += a1.x; acc.w += a1.y;
    }
    float inv = 1.f / fmaxf((float)deg, 1.f);
    acc.x *= inv; acc.y *= inv; acc.z *= inv; acc.w *= inv;
    ((ull*)g_mh)[(size_t)node * 32 + lane] = h4(acc);
}

// ---------------------------------------------------------------------------
// Kernel D: single-term fp16 mma.sync GEMM + bias + LayerNorm + ReLU.
// 512 threads / 16 warps per CTA, warp tile 16x64: same total MMAs, half the
// accumulators per thread (32 regs), DOUBLE the warps/SM for latency hiding
// at unchanged smem (71KB -> 2 CTAs/SM -> 32 warps/SM).
// ---------------------------------------------------------------------------
#define APITCH 272            // bytes per smem row (136 fp16); 17x16B, co-prime
#define S_A    0              // 128*272 = 34816
#define S_B    34816
#define S_BIAS 69632
#define S_GAM  70144
#define S_BET  70656
#define SMEM_TOT 71168
#define S_STAGE 0             // epilogue staging reuses tile region (67.6KB)
#define SPITCH 132

extern "C" __global__ void __launch_bounds__(512, 2)
gemm_mma_kernel(const float* __restrict__ bl,
                const float* __restrict__ gamma,
                const float* __restrict__ beta,
                float* __restrict__ out, int N) {
    extern __shared__ char dsm[];
    uint32_t sb = smem_u32(dsm);
    int tid = threadIdx.x;
    int w = tid >> 5, l = tid & 31;
    int wr = w >> 1, wc = w & 1;            // warp tile: rows wr*16, cols wc*64
    int row0 = blockIdx.x * 128;

    if (tid < 128) {
        ((float*)(dsm + S_BIAS))[tid] = bl[tid];
        ((float*)(dsm + S_GAM))[tid]  = gamma[tid];
        ((float*)(dsm + S_BET))[tid]  = beta[tid];
    }

    float acc[8][4];
#pragma unroll
    for (int b = 0; b < 8; ++b)
#pragma unroll
        for (int c = 0; c < 4; ++c) acc[b][c] = 0.f;

    for (int kt = 0; kt < 2; ++kt) {                 // 2 chunks of K=128
        const __half* srcA = kt ? g_xh : g_mh;
        int kw = kt * 128;                           // k offset within W (256 wide)
        __syncthreads();

        // ---- A fill: 128 rows x 16 x 16B, pure cp.async ----
        for (int i = tid; i < 128 * 16; i += 512) {
            int r = i >> 4, q = i & 15;
            size_t gofs = (size_t)(row0 + r) * 128 + q * 8;
            cpa16(sb + S_A + r * APITCH + q * 16, srcA + gofs);
        }
        // ---- B fill: 128 n-rows x 16 x 16B ----
        for (int i = tid; i < 128 * 16; i += 512) {
            int n = i >> 4, q = i & 15;
            size_t gofs = (size_t)n * 256 + kw + q * 8;
            cpa16(sb + S_B + n * APITCH + q * 16, g_wh + gofs);
        }
        CPA_COMMIT();
        CPA_WAIT0();
        __syncthreads();

        // ---- compute: 8 k16 steps; per warp: 5 LDSM + 8 MMA ----
#pragma unroll
        for (int ks = 0; ks < 8; ++ks) {
            int lrow = (l & 7) + (l & 8);
            int lcol = ks * 16 + ((l & 16) ? 8 : 0);
            uint32_t a[4];
            {
                int row = wr * 16 + lrow;
                ldm4(a, sb + S_A + row * APITCH + lcol * 2);
            }
#pragma unroll
            for (int nb = 0; nb < 4; ++nb) {
                int n = wc * 64 + nb * 16 + lrow;
                uint32_t b[4];
                ldm4(b, sb + S_B + n * APITCH + lcol * 2);
                mma16816(acc[2 * nb],     a, b[0], b[2]);
                mma16816(acc[2 * nb + 1], a, b[1], b[3]);
            }
        }
    }

    // ---- stage accumulators to smem (reuses tile region) ----
    __syncthreads();
    float* stag = (float*)(dsm + S_STAGE);
#pragma unroll
    for (int nf = 0; nf < 8; ++nf) {
        int r = wr * 16 + (l >> 2);
        int c = wc * 64 + nf * 8 + (l & 3) * 2;
        *(float2*)(stag + r * SPITCH + c)       = make_float2(acc[nf][0], acc[nf][1]);
        *(float2*)(stag + (r + 8) * SPITCH + c) = make_float2(acc[nf][2], acc[nf][3]);
    }
    __syncthreads();

    // ---- LN + ReLU: warp w handles rows w*8 .. w*8+7 ----
    const float4* biasS = (const float4*)(dsm + S_BIAS);
    const float4* gamS  = (const float4*)(dsm + S_GAM);
    const float4* betS  = (const float4*)(dsm + S_BET);
    float4 bb = biasS[l], gg = gamS[l], ee = betS[l];

    for (int r = w * 8; r < w * 8 + 8; ++r) {
        float4 v = *(const float4*)(stag + r * SPITCH + l * 4);
        v.x += bb.x; v.y += bb.y; v.z += bb.z; v.w += bb.w;
        float s = v.x + v.y + v.z + v.w;
#pragma unroll
        for (int m = 1; m < 32; m <<= 1) s += __shfl_xor_sync(0xffffffffu, s, m);
        float mu = s * (1.0f / 128.0f);
        float dx = v.x - mu, dy = v.y - mu, dz = v.z - mu, dw = v.w - mu;
        float q = dx * dx + dy * dy + dz * dz + dw * dw;
#pragma unroll
        for (int m = 1; m < 32; m <<= 1) q += __shfl_xor_sync(0xffffffffu, q, m);
        float rstd = rsqrtf(q * (1.0f / 128.0f) + 1e-5f);

        int g = row0 + r;
        if (g < N) {
            float4 o;
            o.x = fmaxf(fmaf(dx * rstd, gg.x, ee.x), 0.f);
            o.y = fmaxf(fmaf(dy * rstd, gg.y, ee.y), 0.f);
            o.z = fmaxf(fmaf(dz * rstd, gg.z, ee.z), 0.f);
            o.w = fmaxf(fmaf(dw * rstd, gg.w, ee.w), 0.f);
            *(float4*)(out + (size_t)g * 128 + l * 4) = o;
        }
    }
}

// ---------------------------------------------------------------------------
// Launch: prep, build+xprep (fused grid), pull, gemm.
// ---------------------------------------------------------------------------
extern "C" void kernel_launch(void* const* d_in, const int* in_sizes, int n_in,
                              void* d_out, int out_size) {
    const float* x      = (const float*)d_in[0];
    const void*  ei     = d_in[1];
    const float* Wl     = (const float*)d_in[2];
    const float* bl     = (const float*)d_in[3];
    const float* Wr     = (const float*)d_in[4];
    const float* gamma  = (const float*)d_in[5];
    const float* beta   = (const float*)d_in[6];
    float* out          = (float*)d_out;

    int N = in_sizes[0] / DIM;
    int E = in_sizes[1] / 2;

    cudaFuncSetAttribute(gemm_mma_kernel, cudaFuncAttributeMaxDynamicSharedMemorySize, SMEM_TOT);

    {
        int total = (N > 128 * 256) ? N : 128 * 256;
        prep_kernel<<<(total + 255) / 256, 256>>>(ei, E, N, Wl, Wr);
    }
    {
        int bb = BBLK(E);
        build_xprep_kernel<<<bb + XBLK, 256>>>(ei, x, E, N, bb);
    }
    {
        int blocks = (NPAD + 7) / 8;
        pull_kernel<<<blocks, 256>>>(N);
    }
    {
        int blocks = (N + 127) / 128;
        gemm_mma_kernel<<<blocks, 512, SMEM_TOT>>>(bl, gamma, beta, out, N);
    }
}